// round 1
// baseline (speedup 1.0000x reference)
#include <cuda_runtime.h>
#include <math.h>

#define N_NODES 50000
#define N_EDGES 800000

// ---------------- scratch (no cudaMalloc allowed) ----------------
__device__ float g_q[N_NODES * 128];
__device__ float g_k[N_NODES * 128];
__device__ float g_v[N_NODES * 128];
__device__ float g_skip[N_NODES * 32];
__device__ float g_msg[N_NODES * 128];   // sum over edges of (v+e)*p
__device__ float g_den[N_NODES * 4];     // sum over edges of p, per head

// ================= GEMM: [N,256] x [256,416] -> q,k,v,skip =================
// A = y0 = [x, x*t] built on the fly. BM=128, BN=64, BK=16, 256 threads,
// 8x4 register tile per thread.
#define BM 128
#define BN 64
#define BK 16

__global__ void __launch_bounds__(256) gemm_qkvs(
    const float* __restrict__ x, const float* __restrict__ t,
    const float* __restrict__ Wq, const float* __restrict__ bq,
    const float* __restrict__ Wk, const float* __restrict__ bk,
    const float* __restrict__ Wv, const float* __restrict__ bv,
    const float* __restrict__ Ws, const float* __restrict__ bs,
    int n)
{
    __shared__ float As[BK][BM + 4];   // k-major, padded (132 floats = 528B, 16B aligned rows)
    __shared__ float Bs[BK][BN];

    const int m0 = blockIdx.x * BM;
    const int j0 = blockIdx.y * BN;      // global output column (0..447, valid < 416)
    const int tid = threadIdx.x;
    const int tx = tid & 15;             // 16 col-threads * TN=4 -> 64 cols
    const int ty = tid >> 4;             // 16 row-threads * TM=8 -> 128 rows

    // select weight matrix for this 64-wide column block (blocks never straddle)
    const float* Bmat; const float* bias; float* outp; int jb, bw;
    if (j0 < 128)      { Bmat = Wq; bias = bq; outp = g_q;    jb = j0;       bw = 128; }
    else if (j0 < 256) { Bmat = Wk; bias = bk; outp = g_k;    jb = j0 - 128; bw = 128; }
    else if (j0 < 384) { Bmat = Wv; bias = bv; outp = g_v;    jb = j0 - 256; bw = 128; }
    else               { Bmat = Ws; bias = bs; outp = g_skip; jb = 0;        bw = 32;  }

    float acc[8][4];
    #pragma unroll
    for (int r = 0; r < 8; r++)
        #pragma unroll
        for (int c = 0; c < 4; c++) acc[r][c] = 0.f;

    for (int k0 = 0; k0 < 256; k0 += BK) {
        // ---- load A tile (y0 on the fly): thread (ka = tid&15, m = tid>>4 + i*16)
        {
            const int ka = tid & 15;
            const int kg = k0 + ka;
            #pragma unroll
            for (int i = 0; i < 8; i++) {
                const int m = (tid >> 4) + i * 16;
                const int mg = m0 + m;
                float a = 0.f;
                if (mg < n) {
                    if (kg < 128) a = x[mg * 128 + kg];
                    else          a = x[mg * 128 + (kg - 128)] * t[mg];
                }
                As[ka][m] = a;
            }
        }
        // ---- load B tile: thread (j = tid&63, kb = tid>>6 + i*4), zero-fill OOB (skip block)
        {
            const int j = tid & 63;
            #pragma unroll
            for (int i = 0; i < 4; i++) {
                const int kb = (tid >> 6) + i * 4;
                const int jj = jb + j;
                float b = 0.f;
                if (jj < bw) b = Bmat[(k0 + kb) * bw + jj];
                Bs[kb][j] = b;
            }
        }
        __syncthreads();

        #pragma unroll
        for (int kk = 0; kk < BK; kk++) {
            const float4 a0 = *(const float4*)&As[kk][ty * 8];
            const float4 a1 = *(const float4*)&As[kk][ty * 8 + 4];
            const float4 b0 = *(const float4*)&Bs[kk][tx * 4];
            const float av[8] = {a0.x, a0.y, a0.z, a0.w, a1.x, a1.y, a1.z, a1.w};
            const float bv4[4] = {b0.x, b0.y, b0.z, b0.w};
            #pragma unroll
            for (int r = 0; r < 8; r++)
                #pragma unroll
                for (int c = 0; c < 4; c++)
                    acc[r][c] = fmaf(av[r], bv4[c], acc[r][c]);
        }
        __syncthreads();
    }

    // ---- epilogue: bias + store (float4)
    const int jj = jb + tx * 4;
    if (jj < bw) {
        const float4 bb = *(const float4*)&bias[jj];
        #pragma unroll
        for (int r = 0; r < 8; r++) {
            const int mg = m0 + ty * 8 + r;
            if (mg < n) {
                float4 o;
                o.x = acc[r][0] + bb.x;
                o.y = acc[r][1] + bb.y;
                o.z = acc[r][2] + bb.z;
                o.w = acc[r][3] + bb.w;
                *(float4*)&outp[mg * bw + jj] = o;
            }
        }
    }
}

// ================= Edge pass: one warp per edge ============================
// Softmax shift (segment_max) is algebraically redundant: attn = exp(a)/sum exp(a).
// alpha here is O(1), so no overflow concern. Accumulate p and (v+e)*p.
__global__ void __launch_bounds__(256) edge_kernel(
    const int* __restrict__ ei, const float* __restrict__ ew,
    const float* __restrict__ We, const float* __restrict__ be,
    int nE)
{
    const int e = (int)((blockIdx.x * (unsigned)blockDim.x + threadIdx.x) >> 5);
    const int lane = threadIdx.x & 31;
    if (e >= nE) return;

    const int src = ei[e];
    const int dst = ei[nE + e];
    const float wt = ew[e];

    const float4 We4 = ((const float4*)We)[lane];
    const float4 be4 = ((const float4*)be)[lane];
    float4 e4;
    e4.x = fmaf(wt, We4.x, be4.x);
    e4.y = fmaf(wt, We4.y, be4.y);
    e4.z = fmaf(wt, We4.z, be4.z);
    e4.w = fmaf(wt, We4.w, be4.w);

    const float4 qv = ((const float4*)g_q)[dst * 32 + lane];
    const float4 kv = ((const float4*)g_k)[src * 32 + lane];
    const float4 vv = ((const float4*)g_v)[src * 32 + lane];

    float s = qv.x * (kv.x + e4.x) + qv.y * (kv.y + e4.y)
            + qv.z * (kv.z + e4.z) + qv.w * (kv.w + e4.w);
    // reduce over the 8-lane group owning head h = lane>>3
    s += __shfl_xor_sync(0xffffffffu, s, 1);
    s += __shfl_xor_sync(0xffffffffu, s, 2);
    s += __shfl_xor_sync(0xffffffffu, s, 4);

    const float p = __expf(s * 0.17677669529663689f);  // 1/sqrt(32)

    if ((lane & 7) == 0)
        atomicAdd(&g_den[dst * 4 + (lane >> 3)], p);

    float4 msg;
    msg.x = (vv.x + e4.x) * p;
    msg.y = (vv.y + e4.y) * p;
    msg.z = (vv.z + e4.z) * p;
    msg.w = (vv.w + e4.w) * p;
    float* dp = &g_msg[(size_t)dst * 128 + lane * 4];
    asm volatile("red.global.add.v4.f32 [%0], {%1,%2,%3,%4};"
                 :: "l"(dp), "f"(msg.x), "f"(msg.y), "f"(msg.z), "f"(msg.w)
                 : "memory");
}

// ================= Epilogue: normalize, mean heads, skip, MLP, output ======
// One warp per node (4 nodes per warp, 32 nodes per 256-thread block).
__global__ void __launch_bounds__(256) epilogue_kernel(
    const float* __restrict__ x,
    const float* __restrict__ Wmlp, const float* __restrict__ bmlp,
    float* __restrict__ out, int n)
{
    __shared__ float w_sh[32 * 256];
    __shared__ float bm_sh[256];
    for (int i = threadIdx.x; i < 32 * 256; i += 256) w_sh[i] = Wmlp[i];
    if (threadIdx.x < 256) bm_sh[threadIdx.x] = bmlp[threadIdx.x];
    __syncthreads();

    const int warp = threadIdx.x >> 5;
    const int lane = threadIdx.x & 31;
    const int nodeBase = blockIdx.x * 32 + warp * 4;

    for (int i = 0; i < 4; i++) {
        const int nn = nodeBase + i;      // warp-uniform
        if (nn >= n) continue;

        const float4 den = *(const float4*)&g_den[nn * 4];
        const float d0 = den.x + 1e-16f, d1 = den.y + 1e-16f,
                    d2 = den.z + 1e-16f, d3 = den.w + 1e-16f;
        float z = g_msg[nn * 128 +   0 + lane] / d0
                + g_msg[nn * 128 +  32 + lane] / d1
                + g_msg[nn * 128 +  64 + lane] / d2
                + g_msg[nn * 128 +  96 + lane] / d3;
        z = z * 0.25f + g_skip[nn * 32 + lane];   // bskip already folded in GEMM
        z = tanhf(z);                              // lane holds y[d = lane]

        float accS[4] = {0.f, 0.f, 0.f, 0.f};
        float accH[4] = {0.f, 0.f, 0.f, 0.f};
        #pragma unroll
        for (int d = 0; d < 32; d++) {
            const float zb = __shfl_sync(0xffffffffu, z, d);
            #pragma unroll
            for (int k = 0; k < 4; k++) {
                accS[k] = fmaf(zb, w_sh[d * 256 + lane + 32 * k], accS[k]);
                accH[k] = fmaf(zb, w_sh[d * 256 + 128 + lane + 32 * k], accH[k]);
            }
        }
        #pragma unroll
        for (int k = 0; k < 4; k++) {
            const int c = lane + 32 * k;
            const float sc = tanhf(accS[k] + bm_sh[c]);
            const float sh = tanhf(accH[k] + bm_sh[128 + c]);
            out[nn * 128 + c] = fmaf(x[nn * 128 + c], sc, sh);
        }
    }
}

// ================= launch ==================================================
extern "C" void kernel_launch(void* const* d_in, const int* in_sizes, int n_in,
                              void* d_out, int out_size)
{
    const float* x     = (const float*)d_in[0];
    const float* t     = (const float*)d_in[1];
    const int*   ei    = (const int*)  d_in[2];
    const float* ew    = (const float*)d_in[3];
    const float* Wq    = (const float*)d_in[4];
    const float* bq    = (const float*)d_in[5];
    const float* Wk    = (const float*)d_in[6];
    const float* bk    = (const float*)d_in[7];
    const float* Wv    = (const float*)d_in[8];
    const float* bv    = (const float*)d_in[9];
    const float* We    = (const float*)d_in[10];
    const float* be    = (const float*)d_in[11];
    const float* Wskip = (const float*)d_in[12];
    const float* bskip = (const float*)d_in[13];
    const float* Wmlp  = (const float*)d_in[14];
    const float* bmlp  = (const float*)d_in[15];
    float* out = (float*)d_out;

    const int n  = in_sizes[0] / 128;
    const int nE = in_sizes[3];

    void *msgPtr = nullptr, *denPtr = nullptr;
    cudaGetSymbolAddress(&msgPtr, g_msg);
    cudaGetSymbolAddress(&denPtr, g_den);
    cudaMemsetAsync(msgPtr, 0, (size_t)n * 128 * sizeof(float));
    cudaMemsetAsync(denPtr, 0, (size_t)n * 4 * sizeof(float));

    dim3 g1((n + BM - 1) / BM, 7);
    gemm_qkvs<<<g1, 256>>>(x, t, Wq, bq, Wk, bk, Wv, bv, Wskip, bskip, n);

    const long long totalThreads = (long long)nE * 32;
    edge_kernel<<<(unsigned)((totalThreads + 255) / 256), 256>>>(ei, ew, We, be, nE);

    epilogue_kernel<<<(n + 31) / 32, 256>>>(x, Wmlp, bmlp, out, n);
}

// round 2
// speedup vs baseline: 1.7008x; 1.7008x over previous
#include <cuda_runtime.h>
#include <math.h>

#define N_NODES 50000
#define N_EDGES 800000

// ---------------- scratch (no cudaMalloc allowed) ----------------
__device__ float g_q[N_NODES * 128];
__device__ float g_k[N_NODES * 128];
__device__ float g_v[N_NODES * 128];
__device__ float g_skip[N_NODES * 32];
__device__ float g_msg[N_NODES * 128];   // sum over edges of (v+e)*p
__device__ float g_den[N_NODES * 4];     // sum over edges of p, per head

// ================= tf32 tensor-core GEMM ===================================
// C[N,bw] = y0[N,256] @ W[256,bw], y0 = [x, x*t] built on the fly.
// BM=128, BN=128, BK=32. 256 threads = 8 warps, warp tile 32x64,
// mma.sync.m16n8k8.tf32. grid.y: 0=q 1=k 2=v 3=skip(bw=32, zero-padded B).
#define BM 128
#define BN 128
#define BK 32

__device__ __forceinline__ unsigned f2tf(float x) {
    unsigned r;
    asm("cvt.rna.tf32.f32 %0, %1;" : "=r"(r) : "f"(x));
    return r;
}

__device__ __forceinline__ void mma_tf32(float* c, const unsigned* a,
                                         unsigned b0, unsigned b1) {
    asm volatile(
        "mma.sync.aligned.m16n8k8.row.col.f32.tf32.tf32.f32 "
        "{%0,%1,%2,%3}, {%4,%5,%6,%7}, {%8,%9}, {%0,%1,%2,%3};\n"
        : "+f"(c[0]), "+f"(c[1]), "+f"(c[2]), "+f"(c[3])
        : "r"(a[0]), "r"(a[1]), "r"(a[2]), "r"(a[3]), "r"(b0), "r"(b1));
}

__global__ void __launch_bounds__(256, 2) gemm_tf32(
    const float* __restrict__ x, const float* __restrict__ t,
    const float* __restrict__ Wq, const float* __restrict__ bq,
    const float* __restrict__ Wk, const float* __restrict__ bk,
    const float* __restrict__ Wv, const float* __restrict__ bv,
    const float* __restrict__ Ws, const float* __restrict__ bs,
    int n)
{
    __shared__ float As[BM][BK + 4];    // stride 36: frag banks 4g+tig -> conflict-free
    __shared__ float Bs[BK][BN + 8];    // stride 136: frag banks 8*tig+g -> conflict-free

    const int m0 = blockIdx.x * BM;
    const int slice = blockIdx.y;

    const float* Bmat; const float* bias; float* outp; int bw;
    if (slice == 0)      { Bmat = Wq; bias = bq; outp = g_q;    bw = 128; }
    else if (slice == 1) { Bmat = Wk; bias = bk; outp = g_k;    bw = 128; }
    else if (slice == 2) { Bmat = Wv; bias = bv; outp = g_v;    bw = 128; }
    else                 { Bmat = Ws; bias = bs; outp = g_skip; bw = 32;  }

    const int tid = threadIdx.x;
    const int lane = tid & 31;
    const int wid = tid >> 5;
    const int warp_m = wid & 3;      // 4 warps in m
    const int warp_n = wid >> 2;     // 2 warps in n
    const int g = lane >> 2;         // groupID
    const int tig = lane & 3;        // thread-in-group

    float acc[2][8][4];
    #pragma unroll
    for (int mi = 0; mi < 2; mi++)
        #pragma unroll
        for (int ni = 0; ni < 8; ni++)
            #pragma unroll
            for (int c = 0; c < 4; c++) acc[mi][ni][c] = 0.f;

    // staging registers for global->smem prefetch
    float4 ar[4];
    float4 br[4];

    // A load mapping: row = tid>>1 (0..127), 4 float4s at f4 idx (tid&1)*4 + i
    const int a_row = tid >> 1;
    const int a_f4  = (tid & 1) * 4;
    // B load mapping: rows wid + i*8 (0..31), float4 col4 = lane  (32 f4 per row)
    const int b_col4 = tid & 31;

    auto loadA = [&](int k0) {
        const int mg = m0 + a_row;
        const int xbase = (k0 < 128 ? k0 : k0 - 128);
        float mult = 0.f;
        if (mg < n) mult = (k0 < 128) ? 1.f : t[mg];
        const float4* xr = (const float4*)&x[(size_t)(mg < n ? mg : 0) * 128 + xbase];
        #pragma unroll
        for (int i = 0; i < 4; i++) {
            float4 v = xr[a_f4 + i];
            ar[i].x = v.x * mult; ar[i].y = v.y * mult;
            ar[i].z = v.z * mult; ar[i].w = v.w * mult;
        }
    };
    auto storeA = [&]() {
        #pragma unroll
        for (int i = 0; i < 4; i++) {
            float4 v;
            v.x = __uint_as_float(f2tf(ar[i].x));
            v.y = __uint_as_float(f2tf(ar[i].y));
            v.z = __uint_as_float(f2tf(ar[i].z));
            v.w = __uint_as_float(f2tf(ar[i].w));
            *(float4*)&As[a_row][(a_f4 + i) * 4] = v;
        }
    };
    auto loadB = [&](int k0) {
        const int jj = b_col4 * 4;
        #pragma unroll
        for (int i = 0; i < 4; i++) {
            const int row = wid + i * 8;
            if (jj < bw) br[i] = *(const float4*)&Bmat[(size_t)(k0 + row) * bw + jj];
            else         br[i] = make_float4(0.f, 0.f, 0.f, 0.f);
        }
    };
    auto storeB = [&]() {
        const int jj = b_col4 * 4;
        #pragma unroll
        for (int i = 0; i < 4; i++) {
            const int row = wid + i * 8;
            float4 v;
            v.x = __uint_as_float(f2tf(br[i].x));
            v.y = __uint_as_float(f2tf(br[i].y));
            v.z = __uint_as_float(f2tf(br[i].z));
            v.w = __uint_as_float(f2tf(br[i].w));
            *(float4*)&Bs[row][jj] = v;
        }
    };

    // prologue
    loadA(0); loadB(0);
    storeA(); storeB();
    __syncthreads();

    for (int k0 = 0; k0 < 256; k0 += BK) {
        const bool has_next = (k0 + BK) < 256;
        if (has_next) { loadA(k0 + BK); loadB(k0 + BK); }

        #pragma unroll
        for (int ks = 0; ks < 4; ks++) {
            const int kk = ks * 8;
            unsigned afrag[2][4];
            #pragma unroll
            for (int mi = 0; mi < 2; mi++) {
                const int r0 = warp_m * 32 + mi * 16 + g;
                afrag[mi][0] = __float_as_uint(As[r0][kk + tig]);
                afrag[mi][1] = __float_as_uint(As[r0 + 8][kk + tig]);
                afrag[mi][2] = __float_as_uint(As[r0][kk + tig + 4]);
                afrag[mi][3] = __float_as_uint(As[r0 + 8][kk + tig + 4]);
            }
            #pragma unroll
            for (int ni = 0; ni < 8; ni++) {
                const int cb = warp_n * 64 + ni * 8 + g;
                const unsigned b0 = __float_as_uint(Bs[kk + tig][cb]);
                const unsigned b1 = __float_as_uint(Bs[kk + tig + 4][cb]);
                mma_tf32(acc[0][ni], afrag[0], b0, b1);
                mma_tf32(acc[1][ni], afrag[1], b0, b1);
            }
        }
        __syncthreads();
        if (has_next) { storeA(); storeB(); __syncthreads(); }
    }

    // epilogue: bias + store (float2 per c-pair)
    #pragma unroll
    for (int mi = 0; mi < 2; mi++) {
        const int row = warp_m * 32 + mi * 16 + g;
        #pragma unroll
        for (int ni = 0; ni < 8; ni++) {
            const int col = warp_n * 64 + ni * 8 + 2 * tig;
            if (col >= bw) continue;
            const float bb0 = bias[col];
            const float bb1 = bias[col + 1];
            const int mg0 = m0 + row;
            const int mg1 = m0 + row + 8;
            if (mg0 < n) {
                float2 o; o.x = acc[mi][ni][0] + bb0; o.y = acc[mi][ni][1] + bb1;
                *(float2*)&outp[(size_t)mg0 * bw + col] = o;
            }
            if (mg1 < n) {
                float2 o; o.x = acc[mi][ni][2] + bb0; o.y = acc[mi][ni][3] + bb1;
                *(float2*)&outp[(size_t)mg1 * bw + col] = o;
            }
        }
    }
}

// ================= Edge pass: one warp per edge ============================
// Softmax shift (segment_max) is algebraically redundant: attn = exp(a)/sum exp(a).
__global__ void __launch_bounds__(256) edge_kernel(
    const int* __restrict__ ei, const float* __restrict__ ew,
    const float* __restrict__ We, const float* __restrict__ be,
    int nE)
{
    const int e = (int)((blockIdx.x * (unsigned)blockDim.x + threadIdx.x) >> 5);
    const int lane = threadIdx.x & 31;
    if (e >= nE) return;

    const int src = ei[e];
    const int dst = ei[nE + e];
    const float wt = ew[e];

    const float4 We4 = ((const float4*)We)[lane];
    const float4 be4 = ((const float4*)be)[lane];
    float4 e4;
    e4.x = fmaf(wt, We4.x, be4.x);
    e4.y = fmaf(wt, We4.y, be4.y);
    e4.z = fmaf(wt, We4.z, be4.z);
    e4.w = fmaf(wt, We4.w, be4.w);

    const float4 qv = ((const float4*)g_q)[dst * 32 + lane];
    const float4 kv = ((const float4*)g_k)[src * 32 + lane];
    const float4 vv = ((const float4*)g_v)[src * 32 + lane];

    float s = qv.x * (kv.x + e4.x) + qv.y * (kv.y + e4.y)
            + qv.z * (kv.z + e4.z) + qv.w * (kv.w + e4.w);
    s += __shfl_xor_sync(0xffffffffu, s, 1);
    s += __shfl_xor_sync(0xffffffffu, s, 2);
    s += __shfl_xor_sync(0xffffffffu, s, 4);

    const float p = __expf(s * 0.17677669529663689f);  // 1/sqrt(32)

    if ((lane & 7) == 0)
        atomicAdd(&g_den[dst * 4 + (lane >> 3)], p);

    float4 msg;
    msg.x = (vv.x + e4.x) * p;
    msg.y = (vv.y + e4.y) * p;
    msg.z = (vv.z + e4.z) * p;
    msg.w = (vv.w + e4.w) * p;
    float* dp = &g_msg[(size_t)dst * 128 + lane * 4];
    asm volatile("red.global.add.v4.f32 [%0], {%1,%2,%3,%4};"
                 :: "l"(dp), "f"(msg.x), "f"(msg.y), "f"(msg.z), "f"(msg.w)
                 : "memory");
}

// ================= Epilogue: normalize, mean heads, skip, MLP, output ======
__global__ void __launch_bounds__(256) epilogue_kernel(
    const float* __restrict__ x,
    const float* __restrict__ Wmlp, const float* __restrict__ bmlp,
    float* __restrict__ out, int n)
{
    __shared__ float w_sh[32 * 256];
    __shared__ float bm_sh[256];
    for (int i = threadIdx.x; i < 32 * 256; i += 256) w_sh[i] = Wmlp[i];
    if (threadIdx.x < 256) bm_sh[threadIdx.x] = bmlp[threadIdx.x];
    __syncthreads();

    const int warp = threadIdx.x >> 5;
    const int lane = threadIdx.x & 31;
    const int nodeBase = blockIdx.x * 32 + warp * 4;

    for (int i = 0; i < 4; i++) {
        const int nn = nodeBase + i;      // warp-uniform
        if (nn >= n) continue;

        const float4 den = *(const float4*)&g_den[nn * 4];
        const float d0 = den.x + 1e-16f, d1 = den.y + 1e-16f,
                    d2 = den.z + 1e-16f, d3 = den.w + 1e-16f;
        float z = g_msg[nn * 128 +   0 + lane] / d0
                + g_msg[nn * 128 +  32 + lane] / d1
                + g_msg[nn * 128 +  64 + lane] / d2
                + g_msg[nn * 128 +  96 + lane] / d3;
        z = z * 0.25f + g_skip[nn * 32 + lane];   // bskip folded in GEMM
        z = tanhf(z);

        float accS[4] = {0.f, 0.f, 0.f, 0.f};
        float accH[4] = {0.f, 0.f, 0.f, 0.f};
        #pragma unroll
        for (int d = 0; d < 32; d++) {
            const float zb = __shfl_sync(0xffffffffu, z, d);
            #pragma unroll
            for (int k = 0; k < 4; k++) {
                accS[k] = fmaf(zb, w_sh[d * 256 + lane + 32 * k], accS[k]);
                accH[k] = fmaf(zb, w_sh[d * 256 + 128 + lane + 32 * k], accH[k]);
            }
        }
        #pragma unroll
        for (int k = 0; k < 4; k++) {
            const int c = lane + 32 * k;
            const float sc = tanhf(accS[k] + bm_sh[c]);
            const float sh = tanhf(accH[k] + bm_sh[128 + c]);
            out[nn * 128 + c] = fmaf(x[nn * 128 + c], sc, sh);
        }
    }
}

// ================= launch ==================================================
extern "C" void kernel_launch(void* const* d_in, const int* in_sizes, int n_in,
                              void* d_out, int out_size)
{
    const float* x     = (const float*)d_in[0];
    const float* t     = (const float*)d_in[1];
    const int*   ei    = (const int*)  d_in[2];
    const float* ew    = (const float*)d_in[3];
    const float* Wq    = (const float*)d_in[4];
    const float* bq    = (const float*)d_in[5];
    const float* Wk    = (const float*)d_in[6];
    const float* bk    = (const float*)d_in[7];
    const float* Wv    = (const float*)d_in[8];
    const float* bv    = (const float*)d_in[9];
    const float* We    = (const float*)d_in[10];
    const float* be    = (const float*)d_in[11];
    const float* Wskip = (const float*)d_in[12];
    const float* bskip = (const float*)d_in[13];
    const float* Wmlp  = (const float*)d_in[14];
    const float* bmlp  = (const float*)d_in[15];
    float* out = (float*)d_out;

    const int n  = in_sizes[0] / 128;
    const int nE = in_sizes[3];

    void *msgPtr = nullptr, *denPtr = nullptr;
    cudaGetSymbolAddress(&msgPtr, g_msg);
    cudaGetSymbolAddress(&denPtr, g_den);
    cudaMemsetAsync(msgPtr, 0, (size_t)n * 128 * sizeof(float));
    cudaMemsetAsync(denPtr, 0, (size_t)n * 4 * sizeof(float));

    dim3 g1((n + BM - 1) / BM, 4);
    gemm_tf32<<<g1, 256>>>(x, t, Wq, bq, Wk, bk, Wv, bv, Wskip, bskip, n);

    const long long totalThreads = (long long)nE * 32;
    edge_kernel<<<(unsigned)((totalThreads + 255) / 256), 256>>>(ei, ew, We, be, nE);

    epilogue_kernel<<<(n + 31) / 32, 256>>>(x, Wmlp, bmlp, out, n);
}

// round 3
// speedup vs baseline: 1.9460x; 1.1442x over previous
#include <cuda_runtime.h>
#include <math.h>

#define N_NODES 50000
#define N_EDGES 800000

// ---------------- scratch (no cudaMalloc allowed) ----------------
__device__ float g_q[N_NODES * 128];
__device__ float g_k[N_NODES * 128];
__device__ float g_v[N_NODES * 128];
__device__ float g_skip[N_NODES * 32];
__device__ int   g_deg[N_NODES];
__device__ int   g_off[N_NODES];        // exclusive prefix of deg
__device__ int   g_cursor[N_NODES];
__device__ int2  g_csr[N_EDGES];        // (src, bitcast(weight)) grouped by dst
__device__ int   g_bsums[64];

// ================= tf32 tensor-core GEMM ===================================
#define BM 128
#define BN 128
#define BK 32

__device__ __forceinline__ unsigned f2tf(float x) {
    unsigned r;
    asm("cvt.rna.tf32.f32 %0, %1;" : "=r"(r) : "f"(x));
    return r;
}

__device__ __forceinline__ void mma_tf32(float* c, const unsigned* a,
                                         unsigned b0, unsigned b1) {
    asm volatile(
        "mma.sync.aligned.m16n8k8.row.col.f32.tf32.tf32.f32 "
        "{%0,%1,%2,%3}, {%4,%5,%6,%7}, {%8,%9}, {%0,%1,%2,%3};\n"
        : "+f"(c[0]), "+f"(c[1]), "+f"(c[2]), "+f"(c[3])
        : "r"(a[0]), "r"(a[1]), "r"(a[2]), "r"(a[3]), "r"(b0), "r"(b1));
}

__global__ void __launch_bounds__(256, 2) gemm_tf32(
    const float* __restrict__ x, const float* __restrict__ t,
    const float* __restrict__ Wq, const float* __restrict__ bq,
    const float* __restrict__ Wk, const float* __restrict__ bk,
    const float* __restrict__ Wv, const float* __restrict__ bv,
    const float* __restrict__ Ws, const float* __restrict__ bs,
    int n)
{
    __shared__ float As[BM][BK + 4];    // stride 36: frag banks 4g+tig -> conflict-free
    __shared__ float Bs[BK][BN + 8];    // stride 136: frag banks 8*tig+g -> conflict-free

    const int m0 = blockIdx.x * BM;
    const int slice = blockIdx.y;

    const float* Bmat; const float* bias; float* outp; int bw;
    if (slice == 0)      { Bmat = Wq; bias = bq; outp = g_q;    bw = 128; }
    else if (slice == 1) { Bmat = Wk; bias = bk; outp = g_k;    bw = 128; }
    else if (slice == 2) { Bmat = Wv; bias = bv; outp = g_v;    bw = 128; }
    else                 { Bmat = Ws; bias = bs; outp = g_skip; bw = 32;  }

    const int tid = threadIdx.x;
    const int lane = tid & 31;
    const int wid = tid >> 5;
    const int warp_m = wid & 3;
    const int warp_n = wid >> 2;
    const int g = lane >> 2;
    const int tig = lane & 3;

    float acc[2][8][4];
    #pragma unroll
    for (int mi = 0; mi < 2; mi++)
        #pragma unroll
        for (int ni = 0; ni < 8; ni++)
            #pragma unroll
            for (int c = 0; c < 4; c++) acc[mi][ni][c] = 0.f;

    float4 ar[4];
    float4 br[4];

    const int a_row = tid >> 1;
    const int a_f4  = (tid & 1) * 4;
    const int b_col4 = tid & 31;

    auto loadA = [&](int k0) {
        const int mg = m0 + a_row;
        const int xbase = (k0 < 128 ? k0 : k0 - 128);
        float mult = 0.f;
        if (mg < n) mult = (k0 < 128) ? 1.f : t[mg];
        const float4* xr = (const float4*)&x[(size_t)(mg < n ? mg : 0) * 128 + xbase];
        #pragma unroll
        for (int i = 0; i < 4; i++) {
            float4 v = xr[a_f4 + i];
            ar[i].x = v.x * mult; ar[i].y = v.y * mult;
            ar[i].z = v.z * mult; ar[i].w = v.w * mult;
        }
    };
    auto storeA = [&]() {
        #pragma unroll
        for (int i = 0; i < 4; i++) {
            float4 v;
            v.x = __uint_as_float(f2tf(ar[i].x));
            v.y = __uint_as_float(f2tf(ar[i].y));
            v.z = __uint_as_float(f2tf(ar[i].z));
            v.w = __uint_as_float(f2tf(ar[i].w));
            *(float4*)&As[a_row][(a_f4 + i) * 4] = v;
        }
    };
    auto loadB = [&](int k0) {
        const int jj = b_col4 * 4;
        #pragma unroll
        for (int i = 0; i < 4; i++) {
            const int row = wid + i * 8;
            if (jj < bw) br[i] = *(const float4*)&Bmat[(size_t)(k0 + row) * bw + jj];
            else         br[i] = make_float4(0.f, 0.f, 0.f, 0.f);
        }
    };
    auto storeB = [&]() {
        const int jj = b_col4 * 4;
        #pragma unroll
        for (int i = 0; i < 4; i++) {
            const int row = wid + i * 8;
            float4 v;
            v.x = __uint_as_float(f2tf(br[i].x));
            v.y = __uint_as_float(f2tf(br[i].y));
            v.z = __uint_as_float(f2tf(br[i].z));
            v.w = __uint_as_float(f2tf(br[i].w));
            *(float4*)&Bs[row][jj] = v;
        }
    };

    loadA(0); loadB(0);
    storeA(); storeB();
    __syncthreads();

    for (int k0 = 0; k0 < 256; k0 += BK) {
        const bool has_next = (k0 + BK) < 256;
        if (has_next) { loadA(k0 + BK); loadB(k0 + BK); }

        #pragma unroll
        for (int ks = 0; ks < 4; ks++) {
            const int kk = ks * 8;
            unsigned afrag[2][4];
            #pragma unroll
            for (int mi = 0; mi < 2; mi++) {
                const int r0 = warp_m * 32 + mi * 16 + g;
                afrag[mi][0] = __float_as_uint(As[r0][kk + tig]);
                afrag[mi][1] = __float_as_uint(As[r0 + 8][kk + tig]);
                afrag[mi][2] = __float_as_uint(As[r0][kk + tig + 4]);
                afrag[mi][3] = __float_as_uint(As[r0 + 8][kk + tig + 4]);
            }
            #pragma unroll
            for (int ni = 0; ni < 8; ni++) {
                const int cb = warp_n * 64 + ni * 8 + g;
                const unsigned b0 = __float_as_uint(Bs[kk + tig][cb]);
                const unsigned b1 = __float_as_uint(Bs[kk + tig + 4][cb]);
                mma_tf32(acc[0][ni], afrag[0], b0, b1);
                mma_tf32(acc[1][ni], afrag[1], b0, b1);
            }
        }
        __syncthreads();
        if (has_next) { storeA(); storeB(); __syncthreads(); }
    }

    #pragma unroll
    for (int mi = 0; mi < 2; mi++) {
        const int row = warp_m * 32 + mi * 16 + g;
        #pragma unroll
        for (int ni = 0; ni < 8; ni++) {
            const int col = warp_n * 64 + ni * 8 + 2 * tig;
            if (col >= bw) continue;
            const float bb0 = bias[col];
            const float bb1 = bias[col + 1];
            const int mg0 = m0 + row;
            const int mg1 = m0 + row + 8;
            if (mg0 < n) {
                float2 o; o.x = acc[mi][ni][0] + bb0; o.y = acc[mi][ni][1] + bb1;
                *(float2*)&outp[(size_t)mg0 * bw + col] = o;
            }
            if (mg1 < n) {
                float2 o; o.x = acc[mi][ni][2] + bb0; o.y = acc[mi][ni][3] + bb1;
                *(float2*)&outp[(size_t)mg1 * bw + col] = o;
            }
        }
    }
}

// ================= CSR build ===============================================
__global__ void count_deg(const int* __restrict__ ei, int nE) {
    const int e = blockIdx.x * blockDim.x + threadIdx.x;
    if (e < nE) atomicAdd(&g_deg[ei[nE + e]], 1);
}

#define SCAN_B 1024
__global__ void scan1(int n) {
    __shared__ int sh[SCAN_B];
    const int tid = threadIdx.x;
    const int i = blockIdx.x * SCAN_B + tid;
    const int v = (i < n) ? g_deg[i] : 0;
    sh[tid] = v;
    __syncthreads();
    #pragma unroll
    for (int off = 1; off < SCAN_B; off <<= 1) {
        int u = (tid >= off) ? sh[tid - off] : 0;
        __syncthreads();
        sh[tid] += u;
        __syncthreads();
    }
    if (i < n) g_off[i] = sh[tid] - v;   // exclusive
    if (tid == SCAN_B - 1) g_bsums[blockIdx.x] = sh[tid];
}

__global__ void scan2(int nb) {
    __shared__ int sh[64];
    const int tid = threadIdx.x;
    const int v = (tid < nb) ? g_bsums[tid] : 0;
    sh[tid] = v;
    __syncthreads();
    #pragma unroll
    for (int off = 1; off < 64; off <<= 1) {
        int u = (tid >= off) ? sh[tid - off] : 0;
        __syncthreads();
        sh[tid] += u;
        __syncthreads();
    }
    if (tid < nb) g_bsums[tid] = sh[tid] - v;  // exclusive
}

__global__ void scan3(int n) {
    const int i = blockIdx.x * SCAN_B + threadIdx.x;
    if (i < n && blockIdx.x > 0) g_off[i] += g_bsums[blockIdx.x];
}

__global__ void scatter_csr(const int* __restrict__ ei,
                            const float* __restrict__ ew, int nE) {
    const int e = blockIdx.x * blockDim.x + threadIdx.x;
    if (e >= nE) return;
    const int src = ei[e];
    const int dst = ei[nE + e];
    const int pos = g_off[dst] + atomicAdd(&g_cursor[dst], 1);
    int2 sw;
    sw.x = src;
    sw.y = __float_as_int(ew[e]);
    g_csr[pos] = sw;
}

// ============ Fused node pass: attention aggregate + epilogue ==============
// One warp per destination node. lane = h*8 + u owns dims [4u,4u+4) of head h.
__global__ void __launch_bounds__(256) node_kernel(
    const float* __restrict__ x,
    const float* __restrict__ We, const float* __restrict__ be,
    const float* __restrict__ Wmlp, const float* __restrict__ bmlp,
    float* __restrict__ out, int n)
{
    __shared__ float w_sh[32 * 256];
    __shared__ float bm_sh[256];
    for (int i = threadIdx.x; i < 32 * 256; i += 256) w_sh[i] = Wmlp[i];
    if (threadIdx.x < 256) bm_sh[threadIdx.x] = bmlp[threadIdx.x];
    __syncthreads();

    const int warp = threadIdx.x >> 5;
    const int lane = threadIdx.x & 31;
    const int nn = blockIdx.x * 8 + warp;
    if (nn >= n) return;

    const float4 We4 = ((const float4*)We)[lane];
    const float4 be4 = ((const float4*)be)[lane];
    const float4 q4 = ((const float4*)g_q)[nn * 32 + lane];

    const int beg = g_off[nn];
    const int cnt = g_deg[nn];

    float4 macc = make_float4(0.f, 0.f, 0.f, 0.f);
    float dsum = 0.f;

    for (int j = 0; j < cnt; j++) {
        const int2 sw = g_csr[beg + j];
        const int src = sw.x;
        const float wt = __int_as_float(sw.y);
        float4 e4;
        e4.x = fmaf(wt, We4.x, be4.x);
        e4.y = fmaf(wt, We4.y, be4.y);
        e4.z = fmaf(wt, We4.z, be4.z);
        e4.w = fmaf(wt, We4.w, be4.w);
        const float4 kv = ((const float4*)g_k)[src * 32 + lane];
        const float4 vv = ((const float4*)g_v)[src * 32 + lane];

        float s = q4.x * (kv.x + e4.x) + q4.y * (kv.y + e4.y)
                + q4.z * (kv.z + e4.z) + q4.w * (kv.w + e4.w);
        s += __shfl_xor_sync(0xffffffffu, s, 1);
        s += __shfl_xor_sync(0xffffffffu, s, 2);
        s += __shfl_xor_sync(0xffffffffu, s, 4);

        const float p = __expf(s * 0.17677669529663689f);  // 1/sqrt(32)
        dsum += p;
        macc.x = fmaf(vv.x + e4.x, p, macc.x);
        macc.y = fmaf(vv.y + e4.y, p, macc.y);
        macc.z = fmaf(vv.z + e4.z, p, macc.z);
        macc.w = fmaf(vv.w + e4.w, p, macc.w);
    }

    // normalize per head (dsum is replicated across the head's 8 lanes)
    const float inv = 1.f / (dsum + 1e-16f);
    float4 z4;
    z4.x = macc.x * inv; z4.y = macc.y * inv;
    z4.z = macc.z * inv; z4.w = macc.w * inv;

    // sum over heads: butterfly across lane bits 3,4
    #pragma unroll
    for (int m = 8; m <= 16; m <<= 1) {
        z4.x += __shfl_xor_sync(0xffffffffu, z4.x, m);
        z4.y += __shfl_xor_sync(0xffffffffu, z4.y, m);
        z4.z += __shfl_xor_sync(0xffffffffu, z4.z, m);
        z4.w += __shfl_xor_sync(0xffffffffu, z4.w, m);
    }

    const int u = lane & 7;                 // dims 4u..4u+3
    const float4 sk = ((const float4*)g_skip)[nn * 8 + u];
    float4 y4;
    y4.x = tanhf(z4.x * 0.25f + sk.x);
    y4.y = tanhf(z4.y * 0.25f + sk.y);
    y4.z = tanhf(z4.z * 0.25f + sk.z);
    y4.w = tanhf(z4.w * 0.25f + sk.w);

    // MLP: y[32] @ Wmlp[32,256]
    float accS[4] = {0.f, 0.f, 0.f, 0.f};
    float accH[4] = {0.f, 0.f, 0.f, 0.f};
    #pragma unroll
    for (int uu = 0; uu < 8; uu++) {
        const float b0 = __shfl_sync(0xffffffffu, y4.x, uu);
        const float b1 = __shfl_sync(0xffffffffu, y4.y, uu);
        const float b2 = __shfl_sync(0xffffffffu, y4.z, uu);
        const float b3 = __shfl_sync(0xffffffffu, y4.w, uu);
        const int d0 = 4 * uu;
        #pragma unroll
        for (int k = 0; k < 4; k++) {
            const int c = lane + 32 * k;
            accS[k] = fmaf(b0, w_sh[(d0 + 0) * 256 + c], accS[k]);
            accS[k] = fmaf(b1, w_sh[(d0 + 1) * 256 + c], accS[k]);
            accS[k] = fmaf(b2, w_sh[(d0 + 2) * 256 + c], accS[k]);
            accS[k] = fmaf(b3, w_sh[(d0 + 3) * 256 + c], accS[k]);
            accH[k] = fmaf(b0, w_sh[(d0 + 0) * 256 + 128 + c], accH[k]);
            accH[k] = fmaf(b1, w_sh[(d0 + 1) * 256 + 128 + c], accH[k]);
            accH[k] = fmaf(b2, w_sh[(d0 + 2) * 256 + 128 + c], accH[k]);
            accH[k] = fmaf(b3, w_sh[(d0 + 3) * 256 + 128 + c], accH[k]);
        }
    }
    #pragma unroll
    for (int k = 0; k < 4; k++) {
        const int c = lane + 32 * k;
        const float sc = tanhf(accS[k] + bm_sh[c]);
        const float sh = tanhf(accH[k] + bm_sh[128 + c]);
        out[(size_t)nn * 128 + c] = fmaf(x[(size_t)nn * 128 + c], sc, sh);
    }
}

// ================= launch ==================================================
extern "C" void kernel_launch(void* const* d_in, const int* in_sizes, int n_in,
                              void* d_out, int out_size)
{
    const float* x     = (const float*)d_in[0];
    const float* t     = (const float*)d_in[1];
    const int*   ei    = (const int*)  d_in[2];
    const float* ew    = (const float*)d_in[3];
    const float* Wq    = (const float*)d_in[4];
    const float* bq    = (const float*)d_in[5];
    const float* Wk    = (const float*)d_in[6];
    const float* bk    = (const float*)d_in[7];
    const float* Wv    = (const float*)d_in[8];
    const float* bv    = (const float*)d_in[9];
    const float* We    = (const float*)d_in[10];
    const float* be    = (const float*)d_in[11];
    const float* Wskip = (const float*)d_in[12];
    const float* bskip = (const float*)d_in[13];
    const float* Wmlp  = (const float*)d_in[14];
    const float* bmlp  = (const float*)d_in[15];
    float* out = (float*)d_out;

    const int n  = in_sizes[0] / 128;
    const int nE = in_sizes[3];

    void *degPtr = nullptr, *curPtr = nullptr;
    cudaGetSymbolAddress(&degPtr, g_deg);
    cudaGetSymbolAddress(&curPtr, g_cursor);
    cudaMemsetAsync(degPtr, 0, (size_t)n * sizeof(int));
    cudaMemsetAsync(curPtr, 0, (size_t)n * sizeof(int));

    // CSR build
    count_deg<<<(nE + 255) / 256, 256>>>(ei, nE);
    const int nb = (n + SCAN_B - 1) / SCAN_B;
    scan1<<<nb, SCAN_B>>>(n);
    scan2<<<1, 64>>>(nb);
    scan3<<<nb, SCAN_B>>>(n);
    scatter_csr<<<(nE + 255) / 256, 256>>>(ei, ew, nE);

    // GEMM q,k,v,skip
    dim3 g1((n + BM - 1) / BM, 4);
    gemm_tf32<<<g1, 256>>>(x, t, Wq, bq, Wk, bk, Wv, bv, Wskip, bskip, n);

    // Fused attention + epilogue
    node_kernel<<<(n + 7) / 8, 256>>>(x, We, be, Wmlp, bmlp, out, n);
}

// round 4
// speedup vs baseline: 2.0169x; 1.0364x over previous
#include <cuda_runtime.h>
#include <math.h>

#define N_NODES 50000
#define N_EDGES 800000

// ---------------- scratch (no cudaMalloc allowed) ----------------
__device__ float g_q[N_NODES * 128];
__device__ float g_k[N_NODES * 128];
__device__ float g_v[N_NODES * 128];
__device__ float g_skip[N_NODES * 32];
__device__ int   g_deg[N_NODES];
__device__ int   g_off[N_NODES];        // exclusive prefix; after scatter = inclusive end
__device__ int2  g_csr[N_EDGES];        // (src, bitcast(weight)) grouped by dst
__device__ int   g_bsums[64];

// ================= tf32 tensor-core GEMM ===================================
#define BM 128
#define BN 128
#define BK 32

__device__ __forceinline__ unsigned f2tf(float x) {
    unsigned r;
    asm("cvt.rna.tf32.f32 %0, %1;" : "=r"(r) : "f"(x));
    return r;
}

__device__ __forceinline__ void mma_tf32(float* c, const unsigned* a,
                                         unsigned b0, unsigned b1) {
    asm volatile(
        "mma.sync.aligned.m16n8k8.row.col.f32.tf32.tf32.f32 "
        "{%0,%1,%2,%3}, {%4,%5,%6,%7}, {%8,%9}, {%0,%1,%2,%3};\n"
        : "+f"(c[0]), "+f"(c[1]), "+f"(c[2]), "+f"(c[3])
        : "r"(a[0]), "r"(a[1]), "r"(a[2]), "r"(a[3]), "r"(b0), "r"(b1));
}

__global__ void __launch_bounds__(256, 2) gemm_tf32(
    const float* __restrict__ x, const float* __restrict__ t,
    const float* __restrict__ Wq, const float* __restrict__ bq,
    const float* __restrict__ Wk, const float* __restrict__ bk,
    const float* __restrict__ Wv, const float* __restrict__ bv,
    const float* __restrict__ Ws, const float* __restrict__ bs,
    int n)
{
    __shared__ float As[BM][BK + 4];
    __shared__ float Bs[BK][BN + 8];

    const int m0 = blockIdx.x * BM;
    const int slice = blockIdx.y;

    const float* Bmat; const float* bias; float* outp; int bw;
    if (slice == 0)      { Bmat = Wq; bias = bq; outp = g_q;    bw = 128; }
    else if (slice == 1) { Bmat = Wk; bias = bk; outp = g_k;    bw = 128; }
    else if (slice == 2) { Bmat = Wv; bias = bv; outp = g_v;    bw = 128; }
    else                 { Bmat = Ws; bias = bs; outp = g_skip; bw = 32;  }

    const int tid = threadIdx.x;
    const int lane = tid & 31;
    const int wid = tid >> 5;
    const int warp_m = wid & 3;
    const int warp_n = wid >> 2;
    const int g = lane >> 2;
    const int tig = lane & 3;

    float acc[2][8][4];
    #pragma unroll
    for (int mi = 0; mi < 2; mi++)
        #pragma unroll
        for (int ni = 0; ni < 8; ni++)
            #pragma unroll
            for (int c = 0; c < 4; c++) acc[mi][ni][c] = 0.f;

    float4 ar[4];
    float4 br[4];

    const int a_row = tid >> 1;
    const int a_f4  = (tid & 1) * 4;
    const int b_col4 = tid & 31;

    auto loadA = [&](int k0) {
        const int mg = m0 + a_row;
        const int xbase = (k0 < 128 ? k0 : k0 - 128);
        float mult = 0.f;
        if (mg < n) mult = (k0 < 128) ? 1.f : t[mg];
        const float4* xr = (const float4*)&x[(size_t)(mg < n ? mg : 0) * 128 + xbase];
        #pragma unroll
        for (int i = 0; i < 4; i++) {
            float4 v = xr[a_f4 + i];
            ar[i].x = v.x * mult; ar[i].y = v.y * mult;
            ar[i].z = v.z * mult; ar[i].w = v.w * mult;
        }
    };
    auto storeA = [&]() {
        #pragma unroll
        for (int i = 0; i < 4; i++) {
            float4 v;
            v.x = __uint_as_float(f2tf(ar[i].x));
            v.y = __uint_as_float(f2tf(ar[i].y));
            v.z = __uint_as_float(f2tf(ar[i].z));
            v.w = __uint_as_float(f2tf(ar[i].w));
            *(float4*)&As[a_row][(a_f4 + i) * 4] = v;
        }
    };
    auto loadB = [&](int k0) {
        const int jj = b_col4 * 4;
        #pragma unroll
        for (int i = 0; i < 4; i++) {
            const int row = wid + i * 8;
            if (jj < bw) br[i] = *(const float4*)&Bmat[(size_t)(k0 + row) * bw + jj];
            else         br[i] = make_float4(0.f, 0.f, 0.f, 0.f);
        }
    };
    auto storeB = [&]() {
        const int jj = b_col4 * 4;
        #pragma unroll
        for (int i = 0; i < 4; i++) {
            const int row = wid + i * 8;
            float4 v;
            v.x = __uint_as_float(f2tf(br[i].x));
            v.y = __uint_as_float(f2tf(br[i].y));
            v.z = __uint_as_float(f2tf(br[i].z));
            v.w = __uint_as_float(f2tf(br[i].w));
            *(float4*)&Bs[row][jj] = v;
        }
    };

    loadA(0); loadB(0);
    storeA(); storeB();
    __syncthreads();

    for (int k0 = 0; k0 < 256; k0 += BK) {
        const bool has_next = (k0 + BK) < 256;
        if (has_next) { loadA(k0 + BK); loadB(k0 + BK); }

        #pragma unroll
        for (int ks = 0; ks < 4; ks++) {
            const int kk = ks * 8;
            unsigned afrag[2][4];
            #pragma unroll
            for (int mi = 0; mi < 2; mi++) {
                const int r0 = warp_m * 32 + mi * 16 + g;
                afrag[mi][0] = __float_as_uint(As[r0][kk + tig]);
                afrag[mi][1] = __float_as_uint(As[r0 + 8][kk + tig]);
                afrag[mi][2] = __float_as_uint(As[r0][kk + tig + 4]);
                afrag[mi][3] = __float_as_uint(As[r0 + 8][kk + tig + 4]);
            }
            #pragma unroll
            for (int ni = 0; ni < 8; ni++) {
                const int cb = warp_n * 64 + ni * 8 + g;
                const unsigned b0 = __float_as_uint(Bs[kk + tig][cb]);
                const unsigned b1 = __float_as_uint(Bs[kk + tig + 4][cb]);
                mma_tf32(acc[0][ni], afrag[0], b0, b1);
                mma_tf32(acc[1][ni], afrag[1], b0, b1);
            }
        }
        __syncthreads();
        if (has_next) { storeA(); storeB(); __syncthreads(); }
    }

    #pragma unroll
    for (int mi = 0; mi < 2; mi++) {
        const int row = warp_m * 32 + mi * 16 + g;
        #pragma unroll
        for (int ni = 0; ni < 8; ni++) {
            const int col = warp_n * 64 + ni * 8 + 2 * tig;
            if (col >= bw) continue;
            const float bb0 = bias[col];
            const float bb1 = bias[col + 1];
            const int mg0 = m0 + row;
            const int mg1 = m0 + row + 8;
            if (mg0 < n) {
                float2 o; o.x = acc[mi][ni][0] + bb0; o.y = acc[mi][ni][1] + bb1;
                *(float2*)&outp[(size_t)mg0 * bw + col] = o;
            }
            if (mg1 < n) {
                float2 o; o.x = acc[mi][ni][2] + bb0; o.y = acc[mi][ni][3] + bb1;
                *(float2*)&outp[(size_t)mg1 * bw + col] = o;
            }
        }
    }
}

// ================= CSR build ===============================================
__global__ void count_deg(const int* __restrict__ ei, int nE) {
    const int e = blockIdx.x * blockDim.x + threadIdx.x;
    if (e < nE) atomicAdd(&g_deg[ei[nE + e]], 1);
}

#define SCAN_B 1024
__global__ void scan1(int n) {
    __shared__ int sh[SCAN_B];
    const int tid = threadIdx.x;
    const int i = blockIdx.x * SCAN_B + tid;
    const int v = (i < n) ? g_deg[i] : 0;
    sh[tid] = v;
    __syncthreads();
    #pragma unroll
    for (int off = 1; off < SCAN_B; off <<= 1) {
        int u = (tid >= off) ? sh[tid - off] : 0;
        __syncthreads();
        sh[tid] += u;
        __syncthreads();
    }
    if (i < n) g_off[i] = sh[tid] - v;   // exclusive
    if (tid == SCAN_B - 1) g_bsums[blockIdx.x] = sh[tid];
}

__global__ void scan2(int nb) {
    __shared__ int sh[64];
    const int tid = threadIdx.x;
    const int v = (tid < nb) ? g_bsums[tid] : 0;
    sh[tid] = v;
    __syncthreads();
    #pragma unroll
    for (int off = 1; off < 64; off <<= 1) {
        int u = (tid >= off) ? sh[tid - off] : 0;
        __syncthreads();
        sh[tid] += u;
        __syncthreads();
    }
    if (tid < nb) g_bsums[tid] = sh[tid] - v;  // exclusive
}

__global__ void scan3(int n) {
    const int i = blockIdx.x * SCAN_B + threadIdx.x;
    if (i < n && blockIdx.x > 0) g_off[i] += g_bsums[blockIdx.x];
}

// bump g_off[dst] directly: after this kernel g_off[dst] = inclusive end.
__global__ void scatter_csr(const int* __restrict__ ei,
                            const float* __restrict__ ew, int nE) {
    const int e = blockIdx.x * blockDim.x + threadIdx.x;
    if (e >= nE) return;
    const int src = ei[e];
    const int dst = ei[nE + e];
    const int pos = atomicAdd(&g_off[dst], 1);
    int2 sw;
    sw.x = src;
    sw.y = __float_as_int(ew[e]);
    g_csr[pos] = sw;
}

// ============ Fused node pass: attention aggregate + epilogue ==============
// One warp per destination node; 4-edge software pipeline for MLP.
__global__ void __launch_bounds__(256) node_kernel(
    const float* __restrict__ x,
    const float* __restrict__ We, const float* __restrict__ be,
    const float* __restrict__ Wmlp, const float* __restrict__ bmlp,
    float* __restrict__ out, int n)
{
    __shared__ float w_sh[32 * 256];
    __shared__ float bm_sh[256];
    for (int i = threadIdx.x; i < 32 * 256; i += 256) w_sh[i] = Wmlp[i];
    if (threadIdx.x < 256) bm_sh[threadIdx.x] = bmlp[threadIdx.x];
    __syncthreads();

    const int warp = threadIdx.x >> 5;
    const int lane = threadIdx.x & 31;
    const int nn = blockIdx.x * 8 + warp;
    if (nn >= n) return;

    const float4 We4 = ((const float4*)We)[lane];
    const float4 be4 = ((const float4*)be)[lane];
    const float4 q4 = ((const float4*)g_q)[nn * 32 + lane];

    const int cnt = g_deg[nn];
    const int end = g_off[nn];          // inclusive end (scatter bumped it)
    const int beg = end - cnt;

    float4 macc = make_float4(0.f, 0.f, 0.f, 0.f);
    float dsum = 0.f;

    int j = beg;
    const int lim = beg + (cnt & ~3);
    for (; j < lim; j += 4) {
        // batch-load 4 csr entries then all 8 gathers -> 8 loads in flight
        int2 sw[4];
        #pragma unroll
        for (int i = 0; i < 4; i++) sw[i] = g_csr[j + i];
        float4 kv[4], vv[4];
        #pragma unroll
        for (int i = 0; i < 4; i++) {
            kv[i] = ((const float4*)g_k)[sw[i].x * 32 + lane];
            vv[i] = ((const float4*)g_v)[sw[i].x * 32 + lane];
        }
        float s[4];
        #pragma unroll
        for (int i = 0; i < 4; i++) {
            const float wt = __int_as_float(sw[i].y);
            const float ex = fmaf(wt, We4.x, be4.x);
            const float ey = fmaf(wt, We4.y, be4.y);
            const float ez = fmaf(wt, We4.z, be4.z);
            const float ew_ = fmaf(wt, We4.w, be4.w);
            kv[i].x += ex; kv[i].y += ey; kv[i].z += ez; kv[i].w += ew_;
            vv[i].x += ex; vv[i].y += ey; vv[i].z += ez; vv[i].w += ew_;
            s[i] = q4.x * kv[i].x + q4.y * kv[i].y + q4.z * kv[i].z + q4.w * kv[i].w;
        }
        #pragma unroll
        for (int i = 0; i < 4; i++) {
            s[i] += __shfl_xor_sync(0xffffffffu, s[i], 1);
            s[i] += __shfl_xor_sync(0xffffffffu, s[i], 2);
            s[i] += __shfl_xor_sync(0xffffffffu, s[i], 4);
        }
        #pragma unroll
        for (int i = 0; i < 4; i++) {
            const float p = __expf(s[i] * 0.17677669529663689f);  // 1/sqrt(32)
            dsum += p;
            macc.x = fmaf(vv[i].x, p, macc.x);
            macc.y = fmaf(vv[i].y, p, macc.y);
            macc.z = fmaf(vv[i].z, p, macc.z);
            macc.w = fmaf(vv[i].w, p, macc.w);
        }
    }
    for (; j < end; j++) {
        const int2 sw = g_csr[j];
        const float wt = __int_as_float(sw.y);
        const float ex = fmaf(wt, We4.x, be4.x);
        const float ey = fmaf(wt, We4.y, be4.y);
        const float ez = fmaf(wt, We4.z, be4.z);
        const float ew_ = fmaf(wt, We4.w, be4.w);
        float4 kv = ((const float4*)g_k)[sw.x * 32 + lane];
        float4 vv = ((const float4*)g_v)[sw.x * 32 + lane];
        kv.x += ex; kv.y += ey; kv.z += ez; kv.w += ew_;
        vv.x += ex; vv.y += ey; vv.z += ez; vv.w += ew_;
        float s = q4.x * kv.x + q4.y * kv.y + q4.z * kv.z + q4.w * kv.w;
        s += __shfl_xor_sync(0xffffffffu, s, 1);
        s += __shfl_xor_sync(0xffffffffu, s, 2);
        s += __shfl_xor_sync(0xffffffffu, s, 4);
        const float p = __expf(s * 0.17677669529663689f);
        dsum += p;
        macc.x = fmaf(vv.x, p, macc.x);
        macc.y = fmaf(vv.y, p, macc.y);
        macc.z = fmaf(vv.z, p, macc.z);
        macc.w = fmaf(vv.w, p, macc.w);
    }

    // normalize per head (dsum replicated across the head's 8 lanes)
    const float inv = 1.f / (dsum + 1e-16f);
    float4 z4;
    z4.x = macc.x * inv; z4.y = macc.y * inv;
    z4.z = macc.z * inv; z4.w = macc.w * inv;

    // sum over heads: butterfly across lane bits 3,4
    #pragma unroll
    for (int m = 8; m <= 16; m <<= 1) {
        z4.x += __shfl_xor_sync(0xffffffffu, z4.x, m);
        z4.y += __shfl_xor_sync(0xffffffffu, z4.y, m);
        z4.z += __shfl_xor_sync(0xffffffffu, z4.z, m);
        z4.w += __shfl_xor_sync(0xffffffffu, z4.w, m);
    }

    const int u = lane & 7;                 // dims 4u..4u+3
    const float4 sk = ((const float4*)g_skip)[nn * 8 + u];
    float4 y4;
    y4.x = tanhf(z4.x * 0.25f + sk.x);
    y4.y = tanhf(z4.y * 0.25f + sk.y);
    y4.z = tanhf(z4.z * 0.25f + sk.z);
    y4.w = tanhf(z4.w * 0.25f + sk.w);

    // MLP: y[32] @ Wmlp[32,256]
    float accS[4] = {0.f, 0.f, 0.f, 0.f};
    float accH[4] = {0.f, 0.f, 0.f, 0.f};
    #pragma unroll
    for (int uu = 0; uu < 8; uu++) {
        const float b0 = __shfl_sync(0xffffffffu, y4.x, uu);
        const float b1 = __shfl_sync(0xffffffffu, y4.y, uu);
        const float b2 = __shfl_sync(0xffffffffu, y4.z, uu);
        const float b3 = __shfl_sync(0xffffffffu, y4.w, uu);
        const int d0 = 4 * uu;
        #pragma unroll
        for (int k = 0; k < 4; k++) {
            const int c = lane + 32 * k;
            accS[k] = fmaf(b0, w_sh[(d0 + 0) * 256 + c], accS[k]);
            accS[k] = fmaf(b1, w_sh[(d0 + 1) * 256 + c], accS[k]);
            accS[k] = fmaf(b2, w_sh[(d0 + 2) * 256 + c], accS[k]);
            accS[k] = fmaf(b3, w_sh[(d0 + 3) * 256 + c], accS[k]);
            accH[k] = fmaf(b0, w_sh[(d0 + 0) * 256 + 128 + c], accH[k]);
            accH[k] = fmaf(b1, w_sh[(d0 + 1) * 256 + 128 + c], accH[k]);
            accH[k] = fmaf(b2, w_sh[(d0 + 2) * 256 + 128 + c], accH[k]);
            accH[k] = fmaf(b3, w_sh[(d0 + 3) * 256 + 128 + c], accH[k]);
        }
    }
    #pragma unroll
    for (int k = 0; k < 4; k++) {
        const int c = lane + 32 * k;
        const float sc = tanhf(accS[k] + bm_sh[c]);
        const float sh = tanhf(accH[k] + bm_sh[128 + c]);
        out[(size_t)nn * 128 + c] = fmaf(x[(size_t)nn * 128 + c], sc, sh);
    }
}

// ================= launch ==================================================
extern "C" void kernel_launch(void* const* d_in, const int* in_sizes, int n_in,
                              void* d_out, int out_size)
{
    const float* x     = (const float*)d_in[0];
    const float* t     = (const float*)d_in[1];
    const int*   ei    = (const int*)  d_in[2];
    const float* ew    = (const float*)d_in[3];
    const float* Wq    = (const float*)d_in[4];
    const float* bq    = (const float*)d_in[5];
    const float* Wk    = (const float*)d_in[6];
    const float* bk    = (const float*)d_in[7];
    const float* Wv    = (const float*)d_in[8];
    const float* bv    = (const float*)d_in[9];
    const float* We    = (const float*)d_in[10];
    const float* be    = (const float*)d_in[11];
    const float* Wskip = (const float*)d_in[12];
    const float* bskip = (const float*)d_in[13];
    const float* Wmlp  = (const float*)d_in[14];
    const float* bmlp  = (const float*)d_in[15];
    float* out = (float*)d_out;

    const int n  = in_sizes[0] / 128;
    const int nE = in_sizes[3];

    void *degPtr = nullptr;
    cudaGetSymbolAddress(&degPtr, g_deg);
    cudaMemsetAsync(degPtr, 0, (size_t)n * sizeof(int));

    // CSR build
    count_deg<<<(nE + 255) / 256, 256>>>(ei, nE);
    const int nb = (n + SCAN_B - 1) / SCAN_B;
    scan1<<<nb, SCAN_B>>>(n);
    scan2<<<1, 64>>>(nb);
    scan3<<<nb, SCAN_B>>>(n);
    scatter_csr<<<(nE + 255) / 256, 256>>>(ei, ew, nE);

    // GEMM q,k,v,skip
    dim3 g1((n + BM - 1) / BM, 4);
    gemm_tf32<<<g1, 256>>>(x, t, Wq, bq, Wk, bk, Wv, bv, Wskip, bskip, n);

    // Fused attention + epilogue
    node_kernel<<<(n + 7) / 8, 256>>>(x, We, be, Wmlp, bmlp, out, n);
}